// round 14
// baseline (speedup 1.0000x reference)
#include <cuda_runtime.h>
#include <cuda_fp16.h>
#include <cstdint>

// Problem constants
#define PP 16
#define EE 512
#define HH 512
#define NN 8192

// Tiling: block tile 128x128, 4 warps (2x2), warp tile 64x64, fp16 K-chunk = 64
#define BM 128
#define BN 128
#define BK 64           // half elements per chunk (= 128B per row)
#define NCHUNK 8        // 512 / 64
#define NPASS 4         // 512 / BN
#define STAGES 3
#define THREADS 128

#define ROWB 144                 // padded row stride in bytes (128B data + 16B pad)
#define ASTG (128 * ROWB)        // 18432 B per A stage
#define BSTG (128 * ROWB)        // 18432 B per B stage
#define OFF_B (STAGES * ASTG)
#define OFF_LOG (STAGES * ASTG + STAGES * BSTG)   // 110592
#define SMEM_DYN (OFF_LOG + 512 + 16)

// Device scratch (uint4 => 16B aligned). All values stored as fp16 (RN).
__device__ uint4 g_xh[(size_t)NN * EE / 8];         // x          [N][E]   half
__device__ uint4 g_w0h[(size_t)PP * EE * HH / 8];   // W0^T       [P][H][E] half (K-major)
__device__ uint4 g_w1h[(size_t)PP * HH * HH / 8];   // W1^T       [P][Ho][Hi] half
__device__ uint4 g_h0h[(size_t)PP * NN * HH / 8];   // h0         [P][N][H] half

__device__ __forceinline__ uint32_t h2u(__half2 v) {
    uint32_t u;
    memcpy(&u, &v, 4);
    return u;
}

// ---------------- Prologue kernels ----------------

// x fp32 -> fp16, 8 elements/thread
__global__ void cvt_x_kernel(const float4* __restrict__ x) {
    int j = blockIdx.x * blockDim.x + threadIdx.x;
    if (j >= NN * EE / 8) return;
    float4 a = x[2 * j], b = x[2 * j + 1];
    uint4 o;
    o.x = h2u(__floats2half2_rn(a.x, a.y));
    o.y = h2u(__floats2half2_rn(a.z, a.w));
    o.z = h2u(__floats2half2_rn(b.x, b.y));
    o.w = h2u(__floats2half2_rn(b.z, b.w));
    g_xh[j] = o;
}

// Transpose + fp16-convert W0 [P,E,H]->[P,H,E] and W1 [P,H,H]->[P,Ho,Hi]
__global__ void transpose_w_kernel(const float* __restrict__ W0,
                                   const float* __restrict__ W1) {
    __shared__ float t[32][33];
    const int z = blockIdx.z;  // 0..15: W0 p=z ; 16..31: W1 p=z-16
    const float* src = (z < 16) ? W0 + (size_t)z * EE * HH
                                : W1 + (size_t)(z - 16) * HH * HH;
    __half* dst = (z < 16) ? (__half*)g_w0h + (size_t)z * EE * HH
                           : (__half*)g_w1h + (size_t)(z - 16) * HH * HH;
    const int c0 = blockIdx.x * 32;  // src col (output-neuron n) base
    const int r0 = blockIdx.y * 32;  // src row (input-dim k) base
    const int tx = threadIdx.x, ty = threadIdx.y;
#pragma unroll
    for (int i = ty; i < 32; i += 8)
        t[i][tx] = src[(size_t)(r0 + i) * 512 + c0 + tx];
    __syncthreads();
#pragma unroll
    for (int i = ty; i < 32; i += 8)
        dst[(size_t)(c0 + i) * 512 + r0 + tx] = __float2half_rn(t[tx][i]);
}

// ---------------- Main kernel ----------------

// fp16-accumulator MMA: d(fp16x2 x2) = a*b + c ; chained within one K-chunk only.
__device__ __forceinline__ void mma16h(uint32_t c[2], const uint32_t a[4],
                                       uint32_t b0, uint32_t b1) {
    asm volatile(
        "mma.sync.aligned.m16n8k16.row.col.f16.f16.f16.f16 "
        "{%0,%1}, {%2,%3,%4,%5}, {%6,%7}, {%0,%1};\n"
        : "+r"(c[0]), "+r"(c[1])
        : "r"(a[0]), "r"(a[1]), "r"(a[2]), "r"(a[3]), "r"(b0), "r"(b1));
}

#define LDSM_X4(r, addr)                                                     \
    asm volatile("ldmatrix.sync.aligned.m8n8.x4.shared.b16 {%0,%1,%2,%3}, [%4];" \
                 : "=r"((r)[0]), "=r"((r)[1]), "=r"((r)[2]), "=r"((r)[3])    \
                 : "r"(addr))

// cp.async one K-chunk: A [128 rows x 128B] + B [128 rows x 128B] into a stage.
__device__ __forceinline__ void issue_chunk(const __half* __restrict__ Ag,
                                            const __half* __restrict__ Bg,
                                            int kc, int stage, int tid,
                                            uint32_t sAu, uint32_t sBu) {
    const uint32_t aB = sAu + stage * ASTG;
    const uint32_t bB = sBu + stage * BSTG;
#pragma unroll
    for (int j = 0; j < 8; j++) {             // A: 1024 x 16B over 128 threads
        int idx = tid + j * THREADS;
        int r = idx >> 3, c = idx & 7;
        uint32_t dst = aB + (uint32_t)(r * ROWB + c * 16);
        const __half* src = Ag + (size_t)r * 512 + kc * BK + c * 8;
        asm volatile("cp.async.cg.shared.global [%0], [%1], 16;\n" ::"r"(dst), "l"(src));
    }
#pragma unroll
    for (int j = 0; j < 8; j++) {             // B: 1024 x 16B
        int idx = tid + j * THREADS;
        int n = idx >> 3, c = idx & 7;
        uint32_t dst = bB + (uint32_t)(n * ROWB + c * 16);
        const __half* src = Bg + (size_t)n * 512 + kc * BK + c * 8;
        asm volatile("cp.async.cg.shared.global [%0], [%1], 16;\n" ::"r"(dst), "l"(src));
    }
    asm volatile("cp.async.commit_group;\n");
}

// MMA over one staged chunk. fp16 accumulators chained across the 4 k16-steps
// of this chunk only, then folded into the fp32 master accumulators.
__device__ __forceinline__ void compute_chunk(uint32_t aAddr, uint32_t bAddr,
                                              float acc[4][8][4]) {
    uint32_t hacc[4][8][2];
#pragma unroll
    for (int mt = 0; mt < 4; mt++)
#pragma unroll
        for (int nt = 0; nt < 8; nt++) {
            hacc[mt][nt][0] = 0u;
            hacc[mt][nt][1] = 0u;
        }
#pragma unroll
    for (int kk = 0; kk < 4; kk++) {
        uint32_t af[4][4], bf[4][4];
#pragma unroll
        for (int mt = 0; mt < 4; mt++)
            LDSM_X4(af[mt], aAddr + mt * (16 * ROWB) + kk * 32);
#pragma unroll
        for (int bt = 0; bt < 4; bt++)
            LDSM_X4(bf[bt], bAddr + bt * (16 * ROWB) + kk * 32);
#pragma unroll
        for (int mt = 0; mt < 4; mt++)
#pragma unroll
            for (int bt = 0; bt < 4; bt++) {
                mma16h(hacc[mt][2 * bt],     af[mt], bf[bt][0], bf[bt][2]);
                mma16h(hacc[mt][2 * bt + 1], af[mt], bf[bt][1], bf[bt][3]);
            }
    }
    // Fold fp16 chunk-sums into fp32 master accumulators
#pragma unroll
    for (int mt = 0; mt < 4; mt++)
#pragma unroll
        for (int nt = 0; nt < 8; nt++) {
            __half2 h0, h1;
            memcpy(&h0, &hacc[mt][nt][0], 4);
            memcpy(&h1, &hacc[mt][nt][1], 4);
            float2 lo = __half22float2(h0);
            float2 hi = __half22float2(h1);
            acc[mt][nt][0] += lo.x;
            acc[mt][nt][1] += lo.y;
            acc[mt][nt][2] += hi.x;
            acc[mt][nt][3] += hi.y;
        }
}

// One pass: acc[128x128] += A[128x512] @ B[128x512]^T (both K-major, fp16)
__device__ __forceinline__ void gemm_pass(const __half* __restrict__ Ag,
                                          const __half* __restrict__ Bg,
                                          uint32_t sAu, uint32_t sBu,
                                          uint32_t aAddr0, uint32_t bAddr0,
                                          int tid, float acc[4][8][4]) {
#pragma unroll
    for (int mt = 0; mt < 4; mt++)
#pragma unroll
        for (int nt = 0; nt < 8; nt++)
#pragma unroll
            for (int c = 0; c < 4; c++) acc[mt][nt][c] = 0.f;

    __syncthreads();  // prior pass fully done with all stages
    issue_chunk(Ag, Bg, 0, 0, tid, sAu, sBu);
    issue_chunk(Ag, Bg, 1, 1, tid, sAu, sBu);

    int stage = 0;  // stage of chunk kc == kc % STAGES
    for (int kc = 0; kc < NCHUNK; kc++) {
        if (kc + 1 < NCHUNK) {
            asm volatile("cp.async.wait_group 1;\n" ::);
        } else {
            asm volatile("cp.async.wait_group 0;\n" ::);
        }
        __syncthreads();  // chunk kc resident; all warps done with stage being refilled
        if (kc + 2 < NCHUNK) {
            int s2 = stage + 2;
            if (s2 >= STAGES) s2 -= STAGES;
            issue_chunk(Ag, Bg, kc + 2, s2, tid, sAu, sBu);
        }
        compute_chunk(aAddr0 + stage * ASTG, bAddr0 + stage * BSTG, acc);
        stage = (stage == STAGES - 1) ? 0 : stage + 1;
    }
}

__global__ void __launch_bounds__(THREADS, 2)
mlp_kernel(const float* __restrict__ b0, const float* __restrict__ b1,
           const float* __restrict__ W2, const float* __restrict__ b2,
           float* __restrict__ out) {
    extern __shared__ char smemc[];
    uint32_t sAu;
    asm("{ .reg .u64 t; cvta.to.shared.u64 t, %1; cvt.u32.u64 %0, t; }"
        : "=r"(sAu) : "l"(smemc));
    const uint32_t sBu = sAu + OFF_B;
    float* sLog = (float*)(smemc + OFF_LOG);  // 128 floats

    const int tid = threadIdx.x;
    const int warp = tid >> 5, lane = tid & 31;
    const int wm = warp >> 1, wn = warp & 1;  // 2 x 2 warp grid
    const int qid = lane >> 2, qt = lane & 3;
    const int p = blockIdx.y;
    const int gm0 = blockIdx.x * BM;

    // ldmatrix per-lane bases (stage 0, mt/bt = 0, kk = 0)
    const uint32_t aAddr0 =
        sAu + (uint32_t)((wm * 64 + (lane & 15)) * ROWB + ((lane & 16) ? 16 : 0));
    const uint32_t bAddr0 =
        sBu + (uint32_t)((wn * 64 + (lane & 15)) * ROWB + ((lane & 16) ? 16 : 0));

    const __half* Ax = (const __half*)g_xh + (size_t)gm0 * EE;
    __half* hb = (__half*)g_h0h + ((size_t)p * NN + gm0) * HH;

    float acc[4][8][4];

    // ---------------- Layer 0: h0 = fp16(relu(x @ W0[p] + b0[p])) ----------------
    for (int pass = 0; pass < NPASS; pass++) {
        const int n0 = pass * BN;
        gemm_pass(Ax, (const __half*)g_w0h + (size_t)p * EE * HH + (size_t)n0 * EE,
                  sAu, sBu, aAddr0, bAddr0, tid, acc);

        const float* bptr = b0 + p * HH + n0;
#pragma unroll
        for (int nt = 0; nt < 8; nt++) {
            int col = wn * 64 + nt * 8 + qt * 2;
            float2 bb = *(const float2*)(bptr + col);
#pragma unroll
            for (int mt = 0; mt < 4; mt++) {
                int row = wm * 64 + mt * 16 + qid;
                __half2 o0 = __floats2half2_rn(fmaxf(acc[mt][nt][0] + bb.x, 0.f),
                                               fmaxf(acc[mt][nt][1] + bb.y, 0.f));
                __half2 o1 = __floats2half2_rn(fmaxf(acc[mt][nt][2] + bb.x, 0.f),
                                               fmaxf(acc[mt][nt][3] + bb.y, 0.f));
                *(__half2*)(hb + (size_t)row * HH + n0 + col) = o0;
                *(__half2*)(hb + (size_t)(row + 8) * HH + n0 + col) = o1;
            }
        }
    }

    __threadfence();   // h0 visible in L2 before cp.async.cg reads it
    __syncthreads();
    if (tid < BM) sLog[tid] = 0.f;  // ordered before atomics by gemm_pass's syncs

    // ------- Layer 1 + 2 fused: logit[n] = sum_h relu(h1[n,h]) * W2[p,h] -------
    float lpart[8];
#pragma unroll
    for (int i = 0; i < 8; i++) lpart[i] = 0.f;

    for (int pass = 0; pass < NPASS; pass++) {
        const int n0 = pass * BN;
        gemm_pass(hb, (const __half*)g_w1h + (size_t)p * HH * HH + (size_t)n0 * HH,
                  sAu, sBu, aAddr0, bAddr0, tid, acc);

        const float* bptr = b1 + p * HH + n0;
        const float* wptr = W2 + p * HH + n0;
#pragma unroll
        for (int nt = 0; nt < 8; nt++) {
            int col = wn * 64 + nt * 8 + qt * 2;
            float2 bb = *(const float2*)(bptr + col);
            float2 ww = *(const float2*)(wptr + col);
#pragma unroll
            for (int mt = 0; mt < 4; mt++) {
                float v0 = fmaxf(acc[mt][nt][0] + bb.x, 0.f);
                float v1 = fmaxf(acc[mt][nt][1] + bb.y, 0.f);
                float v2 = fmaxf(acc[mt][nt][2] + bb.x, 0.f);
                float v3 = fmaxf(acc[mt][nt][3] + bb.y, 0.f);
                lpart[2 * mt]     += v0 * ww.x + v1 * ww.y;  // row qid
                lpart[2 * mt + 1] += v2 * ww.x + v3 * ww.y;  // row qid+8
            }
        }
    }

    // Reduce across qt lanes (quad), then smem atomics across warps/nt
#pragma unroll
    for (int i = 0; i < 8; i++) {
        float v = lpart[i];
        v += __shfl_xor_sync(0xffffffffu, v, 1);
        v += __shfl_xor_sync(0xffffffffu, v, 2);
        if (qt == 0) {
            int row = wm * 64 + (i >> 1) * 16 + ((i & 1) ? 8 : 0) + qid;
            atomicAdd(&sLog[row], v);
        }
    }
    __syncthreads();

    if (tid < BM) {
        float logit = sLog[tid] + b2[p];
        out[(size_t)(gm0 + tid) * PP + p] = 1.f / (1.f + expf(-logit));
    }
}

extern "C" void kernel_launch(void* const* d_in, const int* in_sizes, int n_in,
                              void* d_out, int out_size) {
    const float* x  = (const float*)d_in[0];
    const float* W0 = (const float*)d_in[1];
    const float* b0 = (const float*)d_in[2];
    const float* W1 = (const float*)d_in[3];
    const float* b1 = (const float*)d_in[4];
    const float* W2 = (const float*)d_in[5];
    const float* b2 = (const float*)d_in[6];
    float* out = (float*)d_out;

    // Prologue: fp16-convert x; transpose+convert W0, W1 (K-major B operands)
    cvt_x_kernel<<<(NN * EE / 8) / 256, 256>>>((const float4*)x);
    transpose_w_kernel<<<dim3(16, 16, 32), dim3(32, 8)>>>(W0, W1);

    cudaFuncSetAttribute(mlp_kernel, cudaFuncAttributeMaxDynamicSharedMemorySize,
                         SMEM_DYN);
    mlp_kernel<<<dim3(NN / BM, PP), THREADS, SMEM_DYN>>>(b0, b1, W2, b2, out);
}